// round 16
// baseline (speedup 1.0000x reference)
#include <cuda_runtime.h>
#include <cuda_fp16.h>
#include <math.h>
#include <stdint.h>

#define NN    50000
#define NE    800000
#define F1    128
#define H     64
#define NCLS  40
#define NPAD  50176       // = 49 * 1024, multiple of 64

__device__ float  g_A1[(size_t)NPAD * 64];     // layer-1 message accumulator
__device__ __half g_y16[(size_t)NPAD * 128];   // [ x@W0 | x@(W1-W0) ] fp16
__device__ float  g_yroot[(size_t)NPAD * 64];  // x@root1 fp32
__device__ __half g_z16[(size_t)NPAD * 80];    // [ h@W0' | h@(W1'-W0') ] fp16
__device__ float  g_zroot[(size_t)NPAD * 40];  // h@root2 fp32
__device__ __half g_w1[192 * 128];             // proj1 weights, swizzled smem image
__device__ __half g_w2[128 * 64];              // proj2 weights, swizzled smem image
__device__ int    g_count[NPAD];               // per-dst edge count
__device__ int    g_cursor[NPAD];              // local-exclusive scan -> local row end
__device__ int    g_bsum[64];                  // scan block sums (49 used)
__device__ int2   g_edata[NE];                 // dst-grouped (src, bits(v))

// ---------------------------------------------------------------------------
__device__ __forceinline__ void ldsm_x4(uint32_t addr, uint32_t& r0, uint32_t& r1,
                                        uint32_t& r2, uint32_t& r3) {
    asm volatile("ldmatrix.sync.aligned.m8n8.x4.shared.b16 {%0,%1,%2,%3}, [%4];"
                 : "=r"(r0), "=r"(r1), "=r"(r2), "=r"(r3) : "r"(addr));
}

__device__ __forceinline__ void mma16816(float* c, const uint32_t* a, uint32_t b0, uint32_t b1) {
    asm volatile("mma.sync.aligned.m16n8k16.row.col.f32.f16.f16.f32 "
                 "{%0,%1,%2,%3}, {%4,%5,%6,%7}, {%8,%9}, {%0,%1,%2,%3};"
                 : "+f"(c[0]), "+f"(c[1]), "+f"(c[2]), "+f"(c[3])
                 : "r"(a[0]), "r"(a[1]), "r"(a[2]), "r"(a[3]), "r"(b0), "r"(b1));
}

// Inline 49-entry exclusive scan of g_bsum into sboff[64]. Call from all
// threads of a 256-thread block BEFORE any divergent exit; __syncthreads inside.
__device__ __forceinline__ void block_boff_scan(int* sboff, int* stmp, int t) {
    if (t < 64) {
        int v = (t < 49) ? g_bsum[t] : 0;
        stmp[t] = v;
        sboff[t] = v;
    }
    __syncthreads();
    #pragma unroll
    for (int off = 1; off < 64; off <<= 1) {
        int vv = 0;
        if (t < 64 && t >= off) vv = sboff[t - off];
        __syncthreads();
        if (t < 64) sboff[t] += vv;
        __syncthreads();
    }
    if (t < 64) sboff[t] -= stmp[t];   // inclusive -> exclusive
    __syncthreads();
}

// ---------------------------------------------------------------------------
// prep: fp16 swizzled weight images + zero count.
__global__ __launch_bounds__(256) void prep_kernel(
    const float* __restrict__ W1, const float* __restrict__ root1,
    const float* __restrict__ W2, const float* __restrict__ root2)
{
    int gi = blockIdx.x * 256 + threadIdx.x;    // 16 blocks * 256 = 4096
    for (int j = gi; j < NPAD; j += 4096) g_count[j] = 0;

    if (gi < 192 * 16) {
        int o = gi >> 4, g = gi & 15;
        __half hv[8];
        #pragma unroll
        for (int j = 0; j < 8; j++) {
            int k = g * 8 + j;
            float val;
            if (o < 64)       val = __ldg(W1 + k * 64 + o);
            else if (o < 128) { int oo = o - 64;
                                val = __ldg(W1 + 128 * 64 + k * 64 + oo) - __ldg(W1 + k * 64 + oo); }
            else              val = __ldg(root1 + k * 64 + (o - 128));
            hv[j] = __float2half_rn(val);
        }
        *reinterpret_cast<int4*>(g_w1 + (o * 16 + (g ^ (o & 7))) * 8) =
            *reinterpret_cast<int4*>(hv);
    } else if (gi < 192 * 16 + 128 * 8) {
        int gi2 = gi - 192 * 16;
        int o = gi2 >> 3, g = gi2 & 7;
        __half hv[8];
        #pragma unroll
        for (int j = 0; j < 8; j++) {
            int k = g * 8 + j;
            float val;
            if (o < 40)       val = __ldg(W2 + k * 40 + o);
            else if (o < 80)  { int oo = o - 40;
                                val = __ldg(W2 + 64 * 40 + k * 40 + oo) - __ldg(W2 + k * 40 + oo); }
            else if (o < 120) val = __ldg(root2 + k * 40 + (o - 80));
            else              val = 0.f;
            hv[j] = __float2half_rn(val);
        }
        *reinterpret_cast<int4*>(g_w2 + (o * 8 + (g ^ (o & 7))) * 8) =
            *reinterpret_cast<int4*>(hv);
    }
}

// ---------------------------------------------------------------------------
// hist: count[dst]++
__global__ __launch_bounds__(256) void hist_kernel(const int* __restrict__ dst)
{
    int e = blockIdx.x * 256 + threadIdx.x;
    if (e < NE) atomicAdd(g_count + __ldg(dst + e), 1);
}

// ---------------------------------------------------------------------------
// scan1: 49 blocks x 1024 entries -> in-block exclusive scan into g_cursor
// (local coordinates), block totals into g_bsum.
__global__ __launch_bounds__(256) void scan1_kernel()
{
    __shared__ int sh[256];
    int base = blockIdx.x * 1024;
    int t = threadIdx.x;
    int4 c = *reinterpret_cast<const int4*>(g_count + base + 4 * t);
    int s0 = c.x, s01 = c.x + c.y, s012 = s01 + c.z, tot = s012 + c.w;
    sh[t] = tot;
    __syncthreads();
    int run = tot;
    for (int off = 1; off < 256; off <<= 1) {
        int vv = (t >= off) ? sh[t - off] : 0;
        __syncthreads();
        run += vv;
        sh[t] = run;
        __syncthreads();
    }
    int excl = run - tot;
    if (t == 255) g_bsum[blockIdx.x] = run;
    int4 o;
    o.x = excl; o.y = excl + s0; o.z = excl + s01; o.w = excl + s012;
    *reinterpret_cast<int4*>(g_cursor + base + 4 * t) = o;
}

// ---------------------------------------------------------------------------
// reorder: group edges by dst. Computes boff inline.
// After this, g_cursor[n] = LOCAL row end (global end = cursor + boff[n>>10]).
__global__ __launch_bounds__(256) void reorder_kernel(
    const int* __restrict__ src, const int* __restrict__ dst,
    const float* __restrict__ ea)
{
    __shared__ int sboff[64];
    __shared__ int stmp[64];
    int t = threadIdx.x;
    block_boff_scan(sboff, stmp, t);

    int e = blockIdx.x * 256 + t;
    if (e >= NE) return;
    int d = __ldg(dst + e);
    int s = __ldg(src + e);
    float v = __ldg(ea + e);
    int p = atomicAdd(g_cursor + d, 1) + sboff[d >> 10];
    g_edata[p] = make_int2(s, __float_as_int(v));
}

// ---------------------------------------------------------------------------
// proj1 (HMMA): y[n, 0:192] = x[n] @ [W0 | W1-W0 | root1]
__global__ __launch_bounds__(256) void proj1_kernel(const float* __restrict__ x)
{
    extern __shared__ __half hsmem[];
    __half* sA  = hsmem;              // 16 KB
    __half* sBt = hsmem + 64 * 128;   // 48 KB
    const int tid = threadIdx.x;
    const int nb  = blockIdx.x * 64;

    for (int idx = tid; idx < 64 * 16; idx += 256) {
        int row = idx >> 4, g = idx & 15;
        int n = nb + row; if (n > NN - 1) n = NN - 1;
        const float4* xp = reinterpret_cast<const float4*>(x + (size_t)n * F1 + g * 8);
        float4 f0 = __ldg(xp);
        float4 f1 = __ldg(xp + 1);
        __half2 hh[4];
        hh[0] = __floats2half2_rn(f0.x, f0.y);
        hh[1] = __floats2half2_rn(f0.z, f0.w);
        hh[2] = __floats2half2_rn(f1.x, f1.y);
        hh[3] = __floats2half2_rn(f1.z, f1.w);
        *reinterpret_cast<int4*>(sA + (row * 16 + (g ^ (row & 7))) * 8) =
            *reinterpret_cast<int4*>(hh);
    }
    {
        const int4* src4 = reinterpret_cast<const int4*>(g_w1);
        int4* dst4 = reinterpret_cast<int4*>(sBt);
        #pragma unroll
        for (int r = 0; r < 12; r++) dst4[tid + r * 256] = __ldg(src4 + tid + r * 256);
    }
    __syncthreads();

    const int wid = tid >> 5;
    const int l   = tid & 31;
    const int m_base = (wid & 3) * 16;
    const int n_base = (wid >> 2) * 96;

    uint32_t sA_u  = (uint32_t)__cvta_generic_to_shared(sA);
    uint32_t sBt_u = (uint32_t)__cvta_generic_to_shared(sBt);

    const int rowA = m_base + (l & 7) + ((l >> 3) & 1) * 8;
    const int aGsel = (l >> 4) & 1;
    const int bRowOff = (l & 7) + ((l >> 4) & 1) * 8;
    const int bGsel = (l >> 3) & 1;

    float acc[12][4] = {};

    #pragma unroll
    for (int ks = 0; ks < 8; ks++) {
        int g2 = ks * 2;
        uint32_t a[4];
        {
            int gs = g2 + aGsel;
            uint32_t addr = sA_u + (uint32_t)((rowA * 16 + (gs ^ (rowA & 7))) * 16);
            ldsm_x4(addr, a[0], a[1], a[2], a[3]);
        }
        #pragma unroll
        for (int p = 0; p < 6; p++) {
            int nrow = n_base + p * 16 + bRowOff;
            int gs = g2 + bGsel;
            uint32_t addr = sBt_u + (uint32_t)((nrow * 16 + (gs ^ (nrow & 7))) * 16);
            uint32_t b0, b1, b2, b3;
            ldsm_x4(addr, b0, b1, b2, b3);
            mma16816(acc[2 * p],     a, b0, b1);
            mma16816(acc[2 * p + 1], a, b2, b3);
        }
    }

    const int r0 = nb + m_base + (l >> 2);
    const int r1 = r0 + 8;
    const int cofs = (l & 3) * 2;
    #pragma unroll
    for (int p = 0; p < 6; p++) {
        #pragma unroll
        for (int hh = 0; hh < 2; hh++) {
            int t2 = 2 * p + hh;
            int o = n_base + p * 16 + hh * 8 + cofs;
            if (o < 128) {
                *reinterpret_cast<__half2*>(g_y16 + (size_t)r0 * 128 + o) =
                    __floats2half2_rn(acc[t2][0], acc[t2][1]);
                *reinterpret_cast<__half2*>(g_y16 + (size_t)r1 * 128 + o) =
                    __floats2half2_rn(acc[t2][2], acc[t2][3]);
            } else {
                *reinterpret_cast<float2*>(g_yroot + (size_t)r0 * 64 + (o - 128)) =
                    make_float2(acc[t2][0], acc[t2][1]);
                *reinterpret_cast<float2*>(g_yroot + (size_t)r1 * 64 + (o - 128)) =
                    make_float2(acc[t2][2], acc[t2][3]);
            }
        }
    }
}

// ---------------------------------------------------------------------------
// gather1: one warp per node, 4-edge unrolled loads-first inner loop.
// Lanes 0-15 accumulate y0 halves [0,64); lanes 16-31 accumulate v*yd [64,128).
__global__ __launch_bounds__(256) void gather1_kernel()
{
    __shared__ int sboff[64];
    __shared__ int stmp[64];
    int t = threadIdx.x;
    block_boff_scan(sboff, stmp, t);

    int n = blockIdx.x * 8 + (t >> 5);
    if (n >= NN) return;
    int l = t & 31;

    int cnt = __ldg(g_count + n);
    int end = __ldg(g_cursor + n) + sboff[n >> 10];   // global row end
    int e = end - cnt;

    float acc0 = 0.f, acc1 = 0.f, acc2 = 0.f, acc3 = 0.f;
    for (; e + 4 <= end; e += 4) {
        int2 ed0 = __ldg(g_edata + e);
        int2 ed1 = __ldg(g_edata + e + 1);
        int2 ed2 = __ldg(g_edata + e + 2);
        int2 ed3 = __ldg(g_edata + e + 3);
        int2 pa = __ldg(reinterpret_cast<const int2*>(g_y16 + (size_t)ed0.x * 128) + l);
        int2 pb = __ldg(reinterpret_cast<const int2*>(g_y16 + (size_t)ed1.x * 128) + l);
        int2 pc = __ldg(reinterpret_cast<const int2*>(g_y16 + (size_t)ed2.x * 128) + l);
        int2 pd = __ldg(reinterpret_cast<const int2*>(g_y16 + (size_t)ed3.x * 128) + l);
        float s0 = (l < 16) ? 1.f : __int_as_float(ed0.y);
        float s1 = (l < 16) ? 1.f : __int_as_float(ed1.y);
        float s2 = (l < 16) ? 1.f : __int_as_float(ed2.y);
        float s3 = (l < 16) ? 1.f : __int_as_float(ed3.y);
        const __half2* ha = reinterpret_cast<const __half2*>(&pa);
        const __half2* hb = reinterpret_cast<const __half2*>(&pb);
        const __half2* hc = reinterpret_cast<const __half2*>(&pc);
        const __half2* hd = reinterpret_cast<const __half2*>(&pd);
        float2 a0 = __half22float2(ha[0]), a1 = __half22float2(ha[1]);
        float2 b0 = __half22float2(hb[0]), b1 = __half22float2(hb[1]);
        float2 c0 = __half22float2(hc[0]), c1 = __half22float2(hc[1]);
        float2 d0 = __half22float2(hd[0]), d1 = __half22float2(hd[1]);
        acc0 = fmaf(s0, a0.x, acc0); acc0 = fmaf(s1, b0.x, acc0);
        acc0 = fmaf(s2, c0.x, acc0); acc0 = fmaf(s3, d0.x, acc0);
        acc1 = fmaf(s0, a0.y, acc1); acc1 = fmaf(s1, b0.y, acc1);
        acc1 = fmaf(s2, c0.y, acc1); acc1 = fmaf(s3, d0.y, acc1);
        acc2 = fmaf(s0, a1.x, acc2); acc2 = fmaf(s1, b1.x, acc2);
        acc2 = fmaf(s2, c1.x, acc2); acc2 = fmaf(s3, d1.x, acc2);
        acc3 = fmaf(s0, a1.y, acc3); acc3 = fmaf(s1, b1.y, acc3);
        acc3 = fmaf(s2, c1.y, acc3); acc3 = fmaf(s3, d1.y, acc3);
    }
    for (; e < end; e++) {
        int2 ed = __ldg(g_edata + e);
        int2 p = __ldg(reinterpret_cast<const int2*>(g_y16 + (size_t)ed.x * 128) + l);
        float sc = (l < 16) ? 1.f : __int_as_float(ed.y);
        const __half2* h = reinterpret_cast<const __half2*>(&p);
        float2 f0 = __half22float2(h[0]);
        float2 f1 = __half22float2(h[1]);
        acc0 = fmaf(sc, f0.x, acc0);
        acc1 = fmaf(sc, f0.y, acc1);
        acc2 = fmaf(sc, f1.x, acc2);
        acc3 = fmaf(sc, f1.y, acc3);
    }
    acc0 += __shfl_down_sync(0xffffffffu, acc0, 16);
    acc1 += __shfl_down_sync(0xffffffffu, acc1, 16);
    acc2 += __shfl_down_sync(0xffffffffu, acc2, 16);
    acc3 += __shfl_down_sync(0xffffffffu, acc3, 16);
    if (l < 16)
        *reinterpret_cast<float4*>(g_A1 + (size_t)n * 64 + l * 4) =
            make_float4(acc0, acc1, acc2, acc3);
}

// ---------------------------------------------------------------------------
// proj2 (HMMA, fused ELU): h = elu(A1/deg + yroot + bias1) -> fp16 SMEM,
// then z[n, 0:128] = h[n] @ [W0' | W1'-W0' | root2 | 0].
__global__ __launch_bounds__(256) void proj2_kernel(const float* __restrict__ bias1)
{
    __shared__ __half sH[64 * 64];
    __shared__ __half sBt[128 * 64];
    const int tid = threadIdx.x;
    const int nb = blockIdx.x * 64;

    {
        const int4* src4 = reinterpret_cast<const int4*>(g_w2);
        int4* dst4 = reinterpret_cast<int4*>(sBt);
        #pragma unroll
        for (int r = 0; r < 4; r++) dst4[tid + r * 256] = __ldg(src4 + tid + r * 256);
    }

    {
        int row = tid >> 2, gp = tid & 3;
        int n = nb + row;
        float dg = (float)__ldg(g_count + n);
        float inv = __fdividef(1.0f, fmaxf(dg, 1.0f));
        #pragma unroll
        for (int gg = 0; gg < 2; gg++) {
            int g = gp * 2 + gg;
            const float4* ap = reinterpret_cast<const float4*>(g_A1 + (size_t)n * 64 + g * 8);
            const float4* yp = reinterpret_cast<const float4*>(g_yroot + (size_t)n * 64 + g * 8);
            const float4* bp = reinterpret_cast<const float4*>(bias1) + g * 2;
            float4 a0 = ap[0], a1 = ap[1];
            float4 y0 = yp[0], y1 = yp[1];
            float4 b0 = __ldg(bp), b1 = __ldg(bp + 1);
            float hv[8];
            hv[0] = a0.x * inv + y0.x + b0.x;
            hv[1] = a0.y * inv + y0.y + b0.y;
            hv[2] = a0.z * inv + y0.z + b0.z;
            hv[3] = a0.w * inv + y0.w + b0.w;
            hv[4] = a1.x * inv + y1.x + b1.x;
            hv[5] = a1.y * inv + y1.y + b1.y;
            hv[6] = a1.z * inv + y1.z + b1.z;
            hv[7] = a1.w * inv + y1.w + b1.w;
            __half2 hp[4];
            #pragma unroll
            for (int q = 0; q < 4; q++) {
                float u0 = hv[2 * q],     e0v = u0 > 0.f ? u0 : (__expf(u0) - 1.0f);
                float u1 = hv[2 * q + 1], e1v = u1 > 0.f ? u1 : (__expf(u1) - 1.0f);
                hp[q] = __floats2half2_rn(e0v, e1v);
            }
            *reinterpret_cast<int4*>(sH + (row * 8 + (g ^ (row & 7))) * 8) =
                *reinterpret_cast<int4*>(hp);
        }
    }
    __syncthreads();

    const int wid = tid >> 5;
    const int l   = tid & 31;
    const int m_base = (wid & 3) * 16;
    const int n_base = (wid >> 2) * 64;

    uint32_t sH_u  = (uint32_t)__cvta_generic_to_shared(sH);
    uint32_t sBt_u = (uint32_t)__cvta_generic_to_shared(sBt);

    const int rowA = m_base + (l & 7) + ((l >> 3) & 1) * 8;
    const int aGsel = (l >> 4) & 1;
    const int bRowOff = (l & 7) + ((l >> 4) & 1) * 8;
    const int bGsel = (l >> 3) & 1;

    float acc[8][4] = {};

    #pragma unroll
    for (int ks = 0; ks < 4; ks++) {
        int g2 = ks * 2;
        uint32_t a[4];
        {
            int gs = g2 + aGsel;
            uint32_t addr = sH_u + (uint32_t)((rowA * 8 + (gs ^ (rowA & 7))) * 16);
            ldsm_x4(addr, a[0], a[1], a[2], a[3]);
        }
        #pragma unroll
        for (int p = 0; p < 4; p++) {
            int nrow = n_base + p * 16 + bRowOff;
            int gs = g2 + bGsel;
            uint32_t addr = sBt_u + (uint32_t)((nrow * 8 + (gs ^ (nrow & 7))) * 16);
            uint32_t b0, b1, b2, b3;
            ldsm_x4(addr, b0, b1, b2, b3);
            mma16816(acc[2 * p],     a, b0, b1);
            mma16816(acc[2 * p + 1], a, b2, b3);
        }
    }

    const int r0 = nb + m_base + (l >> 2);
    const int r1 = r0 + 8;
    const int cofs = (l & 3) * 2;
    #pragma unroll
    for (int p = 0; p < 4; p++) {
        #pragma unroll
        for (int hh = 0; hh < 2; hh++) {
            int t2 = 2 * p + hh;
            int o = n_base + p * 16 + hh * 8 + cofs;
            if (o < 80) {
                *reinterpret_cast<__half2*>(g_z16 + (size_t)r0 * 80 + o) =
                    __floats2half2_rn(acc[t2][0], acc[t2][1]);
                *reinterpret_cast<__half2*>(g_z16 + (size_t)r1 * 80 + o) =
                    __floats2half2_rn(acc[t2][2], acc[t2][3]);
            } else if (o < 120) {
                *reinterpret_cast<float2*>(g_zroot + (size_t)r0 * 40 + (o - 80)) =
                    make_float2(acc[t2][0], acc[t2][1]);
                *reinterpret_cast<float2*>(g_zroot + (size_t)r1 * 40 + (o - 80)) =
                    make_float2(acc[t2][2], acc[t2][3]);
            }
        }
    }
}

// ---------------------------------------------------------------------------
// gather2 (+ fused final): out[n] = (sum z0[s] + v*zd[s]) / deg + zroot[n] + bias2.
// One warp per node, 4-edge unrolled loads-first. Lanes 0-9: z0; 10-19: zd.
__global__ __launch_bounds__(256) void gather2_kernel(
    const float* __restrict__ bias2, float* __restrict__ out)
{
    __shared__ int sboff[64];
    __shared__ int stmp[64];
    int t = threadIdx.x;
    block_boff_scan(sboff, stmp, t);

    int n = blockIdx.x * 8 + (t >> 5);
    if (n >= NN) return;
    int l = t & 31;

    int cnt = __ldg(g_count + n);
    int end = __ldg(g_cursor + n) + sboff[n >> 10];
    int e = end - cnt;

    int idx = (l < 20) ? l : 0;
    float acc0 = 0.f, acc1 = 0.f, acc2 = 0.f, acc3 = 0.f;
    for (; e + 4 <= end; e += 4) {
        int2 ed0 = __ldg(g_edata + e);
        int2 ed1 = __ldg(g_edata + e + 1);
        int2 ed2 = __ldg(g_edata + e + 2);
        int2 ed3 = __ldg(g_edata + e + 3);
        int2 pa = __ldg(reinterpret_cast<const int2*>(g_z16 + (size_t)ed0.x * 80) + idx);
        int2 pb = __ldg(reinterpret_cast<const int2*>(g_z16 + (size_t)ed1.x * 80) + idx);
        int2 pc = __ldg(reinterpret_cast<const int2*>(g_z16 + (size_t)ed2.x * 80) + idx);
        int2 pd = __ldg(reinterpret_cast<const int2*>(g_z16 + (size_t)ed3.x * 80) + idx);
        float s0 = (l < 10) ? 1.f : ((l < 20) ? __int_as_float(ed0.y) : 0.f);
        float s1 = (l < 10) ? 1.f : ((l < 20) ? __int_as_float(ed1.y) : 0.f);
        float s2 = (l < 10) ? 1.f : ((l < 20) ? __int_as_float(ed2.y) : 0.f);
        float s3 = (l < 10) ? 1.f : ((l < 20) ? __int_as_float(ed3.y) : 0.f);
        const __half2* ha = reinterpret_cast<const __half2*>(&pa);
        const __half2* hb = reinterpret_cast<const __half2*>(&pb);
        const __half2* hc = reinterpret_cast<const __half2*>(&pc);
        const __half2* hd = reinterpret_cast<const __half2*>(&pd);
        float2 a0 = __half22float2(ha[0]), a1 = __half22float2(ha[1]);
        float2 b0 = __half22float2(hb[0]), b1 = __half22float2(hb[1]);
        float2 c0 = __half22float2(hc[0]), c1 = __half22float2(hc[1]);
        float2 d0 = __half22float2(hd[0]), d1 = __half22float2(hd[1]);
        acc0 = fmaf(s0, a0.x, acc0); acc0 = fmaf(s1, b0.x, acc0);
        acc0 = fmaf(s2, c0.x, acc0); acc0 = fmaf(s3, d0.x, acc0);
        acc1 = fmaf(s0, a0.y, acc1); acc1 = fmaf(s1, b0.y, acc1);
        acc1 = fmaf(s2, c0.y, acc1); acc1 = fmaf(s3, d0.y, acc1);
        acc2 = fmaf(s0, a1.x, acc2); acc2 = fmaf(s1, b1.x, acc2);
        acc2 = fmaf(s2, c1.x, acc2); acc2 = fmaf(s3, d1.x, acc2);
        acc3 = fmaf(s0, a1.y, acc3); acc3 = fmaf(s1, b1.y, acc3);
        acc3 = fmaf(s2, c1.y, acc3); acc3 = fmaf(s3, d1.y, acc3);
    }
    for (; e < end; e++) {
        int2 ed = __ldg(g_edata + e);
        int2 p = __ldg(reinterpret_cast<const int2*>(g_z16 + (size_t)ed.x * 80) + idx);
        float sc = (l < 10) ? 1.f : ((l < 20) ? __int_as_float(ed.y) : 0.f);
        const __half2* h = reinterpret_cast<const __half2*>(&p);
        float2 f0 = __half22float2(h[0]);
        float2 f1 = __half22float2(h[1]);
        acc0 = fmaf(sc, f0.x, acc0);
        acc1 = fmaf(sc, f0.y, acc1);
        acc2 = fmaf(sc, f1.x, acc2);
        acc3 = fmaf(sc, f1.y, acc3);
    }
    acc0 += __shfl_down_sync(0xffffffffu, acc0, 10);
    acc1 += __shfl_down_sync(0xffffffffu, acc1, 10);
    acc2 += __shfl_down_sync(0xffffffffu, acc2, 10);
    acc3 += __shfl_down_sync(0xffffffffu, acc3, 10);

    if (l < 10) {
        float inv = __fdividef(1.0f, fmaxf((float)cnt, 1.0f));
        float4 zr = *reinterpret_cast<const float4*>(g_zroot + (size_t)n * 40 + l * 4);
        float4 b  = __ldg(reinterpret_cast<const float4*>(bias2) + l);
        float4 o;
        o.x = acc0 * inv + zr.x + b.x;
        o.y = acc1 * inv + zr.y + b.y;
        o.z = acc2 * inv + zr.z + b.z;
        o.w = acc3 * inv + zr.w + b.w;
        *reinterpret_cast<float4*>(out + (size_t)n * 40 + l * 4) = o;
    }
}

// ---------------------------------------------------------------------------
extern "C" void kernel_launch(void* const* d_in, const int* in_sizes, int n_in,
                              void* d_out, int out_size)
{
    const float* x     = (const float*)d_in[0];
    const int*   eidx  = (const int*)  d_in[1];
    const float* ea    = (const float*)d_in[2];
    const float* W1    = (const float*)d_in[3];
    const float* root1 = (const float*)d_in[4];
    const float* bias1 = (const float*)d_in[5];
    const float* W2    = (const float*)d_in[6];
    const float* root2 = (const float*)d_in[7];
    const float* bias2 = (const float*)d_in[8];
    float* out = (float*)d_out;

    const int* src = eidx;
    const int* dst = eidx + NE;

    const int p1_smem = 256 * 128 * (int)sizeof(__half);   // 65536 B
    cudaFuncSetAttribute(proj1_kernel, cudaFuncAttributeMaxDynamicSharedMemorySize, p1_smem);

    prep_kernel<<<16, 256>>>(W1, root1, W2, root2);
    hist_kernel<<<(NE + 255) / 256, 256>>>(dst);
    scan1_kernel<<<49, 256>>>();
    reorder_kernel<<<(NE + 255) / 256, 256>>>(src, dst, ea);
    proj1_kernel<<<NPAD / 64, 256, p1_smem>>>(x);
    gather1_kernel<<<(NN + 7) / 8, 256>>>();
    proj2_kernel<<<NPAD / 64, 256>>>(bias1);
    gather2_kernel<<<(NN + 7) / 8, 256>>>(bias2, out);
}

// round 17
// speedup vs baseline: 1.1798x; 1.1798x over previous
#include <cuda_runtime.h>
#include <cuda_fp16.h>
#include <math.h>
#include <stdint.h>

#define NN    50000
#define NE    800000
#define F1    128
#define H     64
#define NCLS  40
#define NPAD  50176       // = 49 * 1024, multiple of 64

__device__ float  g_A1[(size_t)NPAD * 64];     // layer-1 message accumulator
__device__ __half g_y16[(size_t)NPAD * 128];   // [ x@W0 | x@(W1-W0) ] fp16
__device__ float  g_yroot[(size_t)NPAD * 64];  // x@root1 fp32
__device__ __half g_z16[(size_t)NPAD * 80];    // [ h@W0' | h@(W1'-W0') ] fp16
__device__ float  g_zroot[(size_t)NPAD * 40];  // h@root2 fp32
__device__ __half g_w1[192 * 128];             // proj1 weights, swizzled smem image
__device__ __half g_w2[128 * 64];              // proj2 weights, swizzled smem image
__device__ int    g_count[NPAD];               // per-dst edge count
__device__ int    g_cursor[NPAD];              // scan -> fill cursor -> row end
__device__ int    g_bsum[64];                  // scan block sums
__device__ int2   g_edata[NE];                 // dst-grouped (src, bits(v))

// ---------------------------------------------------------------------------
__device__ __forceinline__ void ldsm_x4(uint32_t addr, uint32_t& r0, uint32_t& r1,
                                        uint32_t& r2, uint32_t& r3) {
    asm volatile("ldmatrix.sync.aligned.m8n8.x4.shared.b16 {%0,%1,%2,%3}, [%4];"
                 : "=r"(r0), "=r"(r1), "=r"(r2), "=r"(r3) : "r"(addr));
}

__device__ __forceinline__ void mma16816(float* c, const uint32_t* a, uint32_t b0, uint32_t b1) {
    asm volatile("mma.sync.aligned.m16n8k16.row.col.f32.f16.f16.f32 "
                 "{%0,%1,%2,%3}, {%4,%5,%6,%7}, {%8,%9}, {%0,%1,%2,%3};"
                 : "+f"(c[0]), "+f"(c[1]), "+f"(c[2]), "+f"(c[3])
                 : "r"(a[0]), "r"(a[1]), "r"(a[2]), "r"(a[3]), "r"(b0), "r"(b1));
}

// ---------------------------------------------------------------------------
// prep: fp16 swizzled weight images + zero count.
__global__ __launch_bounds__(256) void prep_kernel(
    const float* __restrict__ W1, const float* __restrict__ root1,
    const float* __restrict__ W2, const float* __restrict__ root2)
{
    int gi = blockIdx.x * 256 + threadIdx.x;    // 16 blocks * 256 = 4096
    for (int j = gi; j < NPAD; j += 4096) g_count[j] = 0;

    if (gi < 192 * 16) {
        int o = gi >> 4, g = gi & 15;
        __half hv[8];
        #pragma unroll
        for (int j = 0; j < 8; j++) {
            int k = g * 8 + j;
            float val;
            if (o < 64)       val = __ldg(W1 + k * 64 + o);
            else if (o < 128) { int oo = o - 64;
                                val = __ldg(W1 + 128 * 64 + k * 64 + oo) - __ldg(W1 + k * 64 + oo); }
            else              val = __ldg(root1 + k * 64 + (o - 128));
            hv[j] = __float2half_rn(val);
        }
        *reinterpret_cast<int4*>(g_w1 + (o * 16 + (g ^ (o & 7))) * 8) =
            *reinterpret_cast<int4*>(hv);
    } else if (gi < 192 * 16 + 128 * 8) {
        int gi2 = gi - 192 * 16;
        int o = gi2 >> 3, g = gi2 & 7;
        __half hv[8];
        #pragma unroll
        for (int j = 0; j < 8; j++) {
            int k = g * 8 + j;
            float val;
            if (o < 40)       val = __ldg(W2 + k * 40 + o);
            else if (o < 80)  { int oo = o - 40;
                                val = __ldg(W2 + 64 * 40 + k * 40 + oo) - __ldg(W2 + k * 40 + oo); }
            else if (o < 120) val = __ldg(root2 + k * 40 + (o - 80));
            else              val = 0.f;
            hv[j] = __float2half_rn(val);
        }
        *reinterpret_cast<int4*>(g_w2 + (o * 8 + (g ^ (o & 7))) * 8) =
            *reinterpret_cast<int4*>(hv);
    }
}

// ---------------------------------------------------------------------------
// hist: count[dst]++
__global__ __launch_bounds__(256) void hist_kernel(const int* __restrict__ dst)
{
    int e = blockIdx.x * 256 + threadIdx.x;
    if (e < NE) atomicAdd(g_count + __ldg(dst + e), 1);
}

// ---------------------------------------------------------------------------
// scan1: 49 blocks x 1024 entries -> in-block exclusive scan into g_cursor,
// block totals into g_bsum.
__global__ __launch_bounds__(256) void scan1_kernel()
{
    __shared__ int sh[256];
    int base = blockIdx.x * 1024;
    int t = threadIdx.x;
    int4 c = *reinterpret_cast<const int4*>(g_count + base + 4 * t);
    int s0 = c.x, s01 = c.x + c.y, s012 = s01 + c.z, tot = s012 + c.w;
    sh[t] = tot;
    __syncthreads();
    int run = tot;
    for (int off = 1; off < 256; off <<= 1) {
        int vv = (t >= off) ? sh[t - off] : 0;
        __syncthreads();
        run += vv;
        sh[t] = run;
        __syncthreads();
    }
    int excl = run - tot;
    if (t == 255) g_bsum[blockIdx.x] = run;
    int4 o;
    o.x = excl; o.y = excl + s0; o.z = excl + s01; o.w = excl + s012;
    *reinterpret_cast<int4*>(g_cursor + base + 4 * t) = o;
}

// scan3: each block recomputes the 49-entry block-sum scan in SMEM, then adds.
__global__ __launch_bounds__(256) void scan3_kernel()
{
    __shared__ int svals[64];
    __shared__ int sincl[64];
    int t = threadIdx.x;
    if (t < 64) {
        int v = (t < 49) ? g_bsum[t] : 0;
        svals[t] = v;
        sincl[t] = v;
    }
    __syncthreads();
    for (int off = 1; off < 64; off <<= 1) {
        int vv = 0;
        if (t < 64 && t >= off) vv = sincl[t - off];
        __syncthreads();
        if (t < 64) sincl[t] += vv;
        __syncthreads();
    }
    int i = blockIdx.x * 256 + t;
    if (i < NPAD) {
        int b = i >> 10;
        g_cursor[i] += sincl[b] - svals[b];   // exclusive prefix of block b
    }
}

// ---------------------------------------------------------------------------
// reorder: group edges by dst. After this, cursor[n] = row end.
__global__ __launch_bounds__(256) void reorder_kernel(
    const int* __restrict__ src, const int* __restrict__ dst,
    const float* __restrict__ ea)
{
    int e = blockIdx.x * 256 + threadIdx.x;
    if (e >= NE) return;
    int d = __ldg(dst + e);
    int s = __ldg(src + e);
    float v = __ldg(ea + e);
    int p = atomicAdd(g_cursor + d, 1);
    g_edata[p] = make_int2(s, __float_as_int(v));
}

// ---------------------------------------------------------------------------
// proj1 (HMMA): y[n, 0:192] = x[n] @ [W0 | W1-W0 | root1]
__global__ __launch_bounds__(256) void proj1_kernel(const float* __restrict__ x)
{
    extern __shared__ __half hsmem[];
    __half* sA  = hsmem;              // 16 KB
    __half* sBt = hsmem + 64 * 128;   // 48 KB
    const int tid = threadIdx.x;
    const int nb  = blockIdx.x * 64;

    for (int idx = tid; idx < 64 * 16; idx += 256) {
        int row = idx >> 4, g = idx & 15;
        int n = nb + row; if (n > NN - 1) n = NN - 1;
        const float4* xp = reinterpret_cast<const float4*>(x + (size_t)n * F1 + g * 8);
        float4 f0 = __ldg(xp);
        float4 f1 = __ldg(xp + 1);
        __half2 hh[4];
        hh[0] = __floats2half2_rn(f0.x, f0.y);
        hh[1] = __floats2half2_rn(f0.z, f0.w);
        hh[2] = __floats2half2_rn(f1.x, f1.y);
        hh[3] = __floats2half2_rn(f1.z, f1.w);
        *reinterpret_cast<int4*>(sA + (row * 16 + (g ^ (row & 7))) * 8) =
            *reinterpret_cast<int4*>(hh);
    }
    {
        const int4* src4 = reinterpret_cast<const int4*>(g_w1);
        int4* dst4 = reinterpret_cast<int4*>(sBt);
        #pragma unroll
        for (int r = 0; r < 12; r++) dst4[tid + r * 256] = __ldg(src4 + tid + r * 256);
    }
    __syncthreads();

    const int wid = tid >> 5;
    const int l   = tid & 31;
    const int m_base = (wid & 3) * 16;
    const int n_base = (wid >> 2) * 96;

    uint32_t sA_u  = (uint32_t)__cvta_generic_to_shared(sA);
    uint32_t sBt_u = (uint32_t)__cvta_generic_to_shared(sBt);

    const int rowA = m_base + (l & 7) + ((l >> 3) & 1) * 8;
    const int aGsel = (l >> 4) & 1;
    const int bRowOff = (l & 7) + ((l >> 4) & 1) * 8;
    const int bGsel = (l >> 3) & 1;

    float acc[12][4] = {};

    #pragma unroll
    for (int ks = 0; ks < 8; ks++) {
        int g2 = ks * 2;
        uint32_t a[4];
        {
            int gs = g2 + aGsel;
            uint32_t addr = sA_u + (uint32_t)((rowA * 16 + (gs ^ (rowA & 7))) * 16);
            ldsm_x4(addr, a[0], a[1], a[2], a[3]);
        }
        #pragma unroll
        for (int p = 0; p < 6; p++) {
            int nrow = n_base + p * 16 + bRowOff;
            int gs = g2 + bGsel;
            uint32_t addr = sBt_u + (uint32_t)((nrow * 16 + (gs ^ (nrow & 7))) * 16);
            uint32_t b0, b1, b2, b3;
            ldsm_x4(addr, b0, b1, b2, b3);
            mma16816(acc[2 * p],     a, b0, b1);
            mma16816(acc[2 * p + 1], a, b2, b3);
        }
    }

    const int r0 = nb + m_base + (l >> 2);
    const int r1 = r0 + 8;
    const int cofs = (l & 3) * 2;
    #pragma unroll
    for (int p = 0; p < 6; p++) {
        #pragma unroll
        for (int hh = 0; hh < 2; hh++) {
            int t2 = 2 * p + hh;
            int o = n_base + p * 16 + hh * 8 + cofs;
            if (o < 128) {
                *reinterpret_cast<__half2*>(g_y16 + (size_t)r0 * 128 + o) =
                    __floats2half2_rn(acc[t2][0], acc[t2][1]);
                *reinterpret_cast<__half2*>(g_y16 + (size_t)r1 * 128 + o) =
                    __floats2half2_rn(acc[t2][2], acc[t2][3]);
            } else {
                *reinterpret_cast<float2*>(g_yroot + (size_t)r0 * 64 + (o - 128)) =
                    make_float2(acc[t2][0], acc[t2][1]);
                *reinterpret_cast<float2*>(g_yroot + (size_t)r1 * 64 + (o - 128)) =
                    make_float2(acc[t2][2], acc[t2][3]);
            }
        }
    }
}

// ---------------------------------------------------------------------------
// gather1: one warp per node, 2-edge unrolled loads-first inner loop.
// Lanes 0-15 accumulate y0 halves [0,64); lanes 16-31 accumulate v*yd [64,128).
__global__ __launch_bounds__(256) void gather1_kernel()
{
    int n = blockIdx.x * 8 + (threadIdx.x >> 5);
    if (n >= NN) return;
    int l = threadIdx.x & 31;

    int end = __ldg(g_cursor + n);             // post-reorder: row end
    int cnt = __ldg(g_count + n);
    int e = end - cnt;

    float acc0 = 0.f, acc1 = 0.f, acc2 = 0.f, acc3 = 0.f;
    for (; e + 2 <= end; e += 2) {
        int2 ed0 = __ldg(g_edata + e);
        int2 ed1 = __ldg(g_edata + e + 1);
        int2 pa = __ldg(reinterpret_cast<const int2*>(g_y16 + (size_t)ed0.x * 128) + l);
        int2 pb = __ldg(reinterpret_cast<const int2*>(g_y16 + (size_t)ed1.x * 128) + l);
        float v0 = __int_as_float(ed0.y);
        float v1 = __int_as_float(ed1.y);
        float s0 = (l < 16) ? 1.f : v0;
        float s1 = (l < 16) ? 1.f : v1;
        const __half2* ha = reinterpret_cast<const __half2*>(&pa);
        const __half2* hb = reinterpret_cast<const __half2*>(&pb);
        float2 a0 = __half22float2(ha[0]), a1 = __half22float2(ha[1]);
        float2 b0 = __half22float2(hb[0]), b1 = __half22float2(hb[1]);
        acc0 = fmaf(s0, a0.x, acc0); acc0 = fmaf(s1, b0.x, acc0);
        acc1 = fmaf(s0, a0.y, acc1); acc1 = fmaf(s1, b0.y, acc1);
        acc2 = fmaf(s0, a1.x, acc2); acc2 = fmaf(s1, b1.x, acc2);
        acc3 = fmaf(s0, a1.y, acc3); acc3 = fmaf(s1, b1.y, acc3);
    }
    if (e < end) {
        int2 ed = __ldg(g_edata + e);
        int2 p = __ldg(reinterpret_cast<const int2*>(g_y16 + (size_t)ed.x * 128) + l);
        float v = __int_as_float(ed.y);
        float sc = (l < 16) ? 1.f : v;
        const __half2* h = reinterpret_cast<const __half2*>(&p);
        float2 f0 = __half22float2(h[0]);
        float2 f1 = __half22float2(h[1]);
        acc0 = fmaf(sc, f0.x, acc0);
        acc1 = fmaf(sc, f0.y, acc1);
        acc2 = fmaf(sc, f1.x, acc2);
        acc3 = fmaf(sc, f1.y, acc3);
    }
    acc0 += __shfl_down_sync(0xffffffffu, acc0, 16);
    acc1 += __shfl_down_sync(0xffffffffu, acc1, 16);
    acc2 += __shfl_down_sync(0xffffffffu, acc2, 16);
    acc3 += __shfl_down_sync(0xffffffffu, acc3, 16);
    if (l < 16)
        *reinterpret_cast<float4*>(g_A1 + (size_t)n * 64 + l * 4) =
            make_float4(acc0, acc1, acc2, acc3);
}

// ---------------------------------------------------------------------------
// proj2 (HMMA, fused ELU): h = elu(A1/deg + yroot + bias1) -> fp16 SMEM,
// then z[n, 0:128] = h[n] @ [W0' | W1'-W0' | root2 | 0].
__global__ __launch_bounds__(256) void proj2_kernel(const float* __restrict__ bias1)
{
    __shared__ __half sH[64 * 64];
    __shared__ __half sBt[128 * 64];
    const int tid = threadIdx.x;
    const int nb = blockIdx.x * 64;

    {
        const int4* src4 = reinterpret_cast<const int4*>(g_w2);
        int4* dst4 = reinterpret_cast<int4*>(sBt);
        #pragma unroll
        for (int r = 0; r < 4; r++) dst4[tid + r * 256] = __ldg(src4 + tid + r * 256);
    }

    {
        int row = tid >> 2, gp = tid & 3;
        int n = nb + row;
        float dg = (float)__ldg(g_count + n);
        float inv = __fdividef(1.0f, fmaxf(dg, 1.0f));
        #pragma unroll
        for (int gg = 0; gg < 2; gg++) {
            int g = gp * 2 + gg;
            const float4* ap = reinterpret_cast<const float4*>(g_A1 + (size_t)n * 64 + g * 8);
            const float4* yp = reinterpret_cast<const float4*>(g_yroot + (size_t)n * 64 + g * 8);
            const float4* bp = reinterpret_cast<const float4*>(bias1) + g * 2;
            float4 a0 = ap[0], a1 = ap[1];
            float4 y0 = yp[0], y1 = yp[1];
            float4 b0 = __ldg(bp), b1 = __ldg(bp + 1);
            float hv[8];
            hv[0] = a0.x * inv + y0.x + b0.x;
            hv[1] = a0.y * inv + y0.y + b0.y;
            hv[2] = a0.z * inv + y0.z + b0.z;
            hv[3] = a0.w * inv + y0.w + b0.w;
            hv[4] = a1.x * inv + y1.x + b1.x;
            hv[5] = a1.y * inv + y1.y + b1.y;
            hv[6] = a1.z * inv + y1.z + b1.z;
            hv[7] = a1.w * inv + y1.w + b1.w;
            __half2 hp[4];
            #pragma unroll
            for (int q = 0; q < 4; q++) {
                float u0 = hv[2 * q],     e0v = u0 > 0.f ? u0 : (__expf(u0) - 1.0f);
                float u1 = hv[2 * q + 1], e1v = u1 > 0.f ? u1 : (__expf(u1) - 1.0f);
                hp[q] = __floats2half2_rn(e0v, e1v);
            }
            *reinterpret_cast<int4*>(sH + (row * 8 + (g ^ (row & 7))) * 8) =
                *reinterpret_cast<int4*>(hp);
        }
    }
    __syncthreads();

    const int wid = tid >> 5;
    const int l   = tid & 31;
    const int m_base = (wid & 3) * 16;
    const int n_base = (wid >> 2) * 64;

    uint32_t sH_u  = (uint32_t)__cvta_generic_to_shared(sH);
    uint32_t sBt_u = (uint32_t)__cvta_generic_to_shared(sBt);

    const int rowA = m_base + (l & 7) + ((l >> 3) & 1) * 8;
    const int aGsel = (l >> 4) & 1;
    const int bRowOff = (l & 7) + ((l >> 4) & 1) * 8;
    const int bGsel = (l >> 3) & 1;

    float acc[8][4] = {};

    #pragma unroll
    for (int ks = 0; ks < 4; ks++) {
        int g2 = ks * 2;
        uint32_t a[4];
        {
            int gs = g2 + aGsel;
            uint32_t addr = sH_u + (uint32_t)((rowA * 8 + (gs ^ (rowA & 7))) * 16);
            ldsm_x4(addr, a[0], a[1], a[2], a[3]);
        }
        #pragma unroll
        for (int p = 0; p < 4; p++) {
            int nrow = n_base + p * 16 + bRowOff;
            int gs = g2 + bGsel;
            uint32_t addr = sBt_u + (uint32_t)((nrow * 8 + (gs ^ (nrow & 7))) * 16);
            uint32_t b0, b1, b2, b3;
            ldsm_x4(addr, b0, b1, b2, b3);
            mma16816(acc[2 * p],     a, b0, b1);
            mma16816(acc[2 * p + 1], a, b2, b3);
        }
    }

    const int r0 = nb + m_base + (l >> 2);
    const int r1 = r0 + 8;
    const int cofs = (l & 3) * 2;
    #pragma unroll
    for (int p = 0; p < 4; p++) {
        #pragma unroll
        for (int hh = 0; hh < 2; hh++) {
            int t2 = 2 * p + hh;
            int o = n_base + p * 16 + hh * 8 + cofs;
            if (o < 80) {
                *reinterpret_cast<__half2*>(g_z16 + (size_t)r0 * 80 + o) =
                    __floats2half2_rn(acc[t2][0], acc[t2][1]);
                *reinterpret_cast<__half2*>(g_z16 + (size_t)r1 * 80 + o) =
                    __floats2half2_rn(acc[t2][2], acc[t2][3]);
            } else if (o < 120) {
                *reinterpret_cast<float2*>(g_zroot + (size_t)r0 * 40 + (o - 80)) =
                    make_float2(acc[t2][0], acc[t2][1]);
                *reinterpret_cast<float2*>(g_zroot + (size_t)r1 * 40 + (o - 80)) =
                    make_float2(acc[t2][2], acc[t2][3]);
            }
        }
    }
}

// ---------------------------------------------------------------------------
// gather2 (+ fused final): out[n] = (sum z0[s] + v*zd[s]) / deg + zroot[n] + bias2.
// One warp per node, 2-edge unrolled loads-first. Lanes 0-9: z0; 10-19: zd.
__global__ __launch_bounds__(256) void gather2_kernel(
    const float* __restrict__ bias2, float* __restrict__ out)
{
    int n = blockIdx.x * 8 + (threadIdx.x >> 5);
    if (n >= NN) return;
    int l = threadIdx.x & 31;

    int end = __ldg(g_cursor + n);
    int cnt = __ldg(g_count + n);
    int e = end - cnt;

    int idx = (l < 20) ? l : 0;
    float acc0 = 0.f, acc1 = 0.f, acc2 = 0.f, acc3 = 0.f;
    for (; e + 2 <= end; e += 2) {
        int2 ed0 = __ldg(g_edata + e);
        int2 ed1 = __ldg(g_edata + e + 1);
        int2 pa = __ldg(reinterpret_cast<const int2*>(g_z16 + (size_t)ed0.x * 80) + idx);
        int2 pb = __ldg(reinterpret_cast<const int2*>(g_z16 + (size_t)ed1.x * 80) + idx);
        float v0 = __int_as_float(ed0.y);
        float v1 = __int_as_float(ed1.y);
        float s0 = (l < 10) ? 1.f : ((l < 20) ? v0 : 0.f);
        float s1 = (l < 10) ? 1.f : ((l < 20) ? v1 : 0.f);
        const __half2* ha = reinterpret_cast<const __half2*>(&pa);
        const __half2* hb = reinterpret_cast<const __half2*>(&pb);
        float2 a0 = __half22float2(ha[0]), a1 = __half22float2(ha[1]);
        float2 b0 = __half22float2(hb[0]), b1 = __half22float2(hb[1]);
        acc0 = fmaf(s0, a0.x, acc0); acc0 = fmaf(s1, b0.x, acc0);
        acc1 = fmaf(s0, a0.y, acc1); acc1 = fmaf(s1, b0.y, acc1);
        acc2 = fmaf(s0, a1.x, acc2); acc2 = fmaf(s1, b1.x, acc2);
        acc3 = fmaf(s0, a1.y, acc3); acc3 = fmaf(s1, b1.y, acc3);
    }
    if (e < end) {
        int2 ed = __ldg(g_edata + e);
        int2 p = __ldg(reinterpret_cast<const int2*>(g_z16 + (size_t)ed.x * 80) + idx);
        float v = __int_as_float(ed.y);
        float sc = (l < 10) ? 1.f : ((l < 20) ? v : 0.f);
        const __half2* h = reinterpret_cast<const __half2*>(&p);
        float2 f0 = __half22float2(h[0]);
        float2 f1 = __half22float2(h[1]);
        acc0 = fmaf(sc, f0.x, acc0);
        acc1 = fmaf(sc, f0.y, acc1);
        acc2 = fmaf(sc, f1.x, acc2);
        acc3 = fmaf(sc, f1.y, acc3);
    }
    acc0 += __shfl_down_sync(0xffffffffu, acc0, 10);
    acc1 += __shfl_down_sync(0xffffffffu, acc1, 10);
    acc2 += __shfl_down_sync(0xffffffffu, acc2, 10);
    acc3 += __shfl_down_sync(0xffffffffu, acc3, 10);

    if (l < 10) {
        float inv = __fdividef(1.0f, fmaxf((float)cnt, 1.0f));
        float4 zr = *reinterpret_cast<const float4*>(g_zroot + (size_t)n * 40 + l * 4);
        float4 b  = __ldg(reinterpret_cast<const float4*>(bias2) + l);
        float4 o;
        o.x = acc0 * inv + zr.x + b.x;
        o.y = acc1 * inv + zr.y + b.y;
        o.z = acc2 * inv + zr.z + b.z;
        o.w = acc3 * inv + zr.w + b.w;
        *reinterpret_cast<float4*>(out + (size_t)n * 40 + l * 4) = o;
    }
}

// ---------------------------------------------------------------------------
extern "C" void kernel_launch(void* const* d_in, const int* in_sizes, int n_in,
                              void* d_out, int out_size)
{
    const float* x     = (const float*)d_in[0];
    const int*   eidx  = (const int*)  d_in[1];
    const float* ea    = (const float*)d_in[2];
    const float* W1    = (const float*)d_in[3];
    const float* root1 = (const float*)d_in[4];
    const float* bias1 = (const float*)d_in[5];
    const float* W2    = (const float*)d_in[6];
    const float* root2 = (const float*)d_in[7];
    const float* bias2 = (const float*)d_in[8];
    float* out = (float*)d_out;

    const int* src = eidx;
    const int* dst = eidx + NE;

    const int p1_smem = 256 * 128 * (int)sizeof(__half);   // 65536 B
    cudaFuncSetAttribute(proj1_kernel, cudaFuncAttributeMaxDynamicSharedMemorySize, p1_smem);

    // Side stream + events for fork-join overlap of proj1 with the sort chain.
    // Created per call (host objects); intentionally not destroyed mid-capture.
    cudaStream_t s2;
    cudaStreamCreateWithFlags(&s2, cudaStreamNonBlocking);
    cudaEvent_t evFork, evJoin;
    cudaEventCreateWithFlags(&evFork, cudaEventDisableTiming);
    cudaEventCreateWithFlags(&evJoin, cudaEventDisableTiming);

    prep_kernel<<<16, 256>>>(W1, root1, W2, root2);

    // fork: proj1 on side stream (depends only on prep)
    cudaEventRecord(evFork, 0);
    cudaStreamWaitEvent(s2, evFork, 0);
    proj1_kernel<<<NPAD / 64, 256, p1_smem, s2>>>(x);

    // sort chain on main stream
    hist_kernel<<<(NE + 255) / 256, 256>>>(dst);
    scan1_kernel<<<49, 256>>>();
    scan3_kernel<<<(NPAD + 255) / 256, 256>>>();
    reorder_kernel<<<(NE + 255) / 256, 256>>>(src, dst, ea);

    // join: gather1 needs both proj1 (y16) and reorder (edata)
    cudaEventRecord(evJoin, s2);
    cudaStreamWaitEvent(0, evJoin, 0);

    gather1_kernel<<<(NN + 7) / 8, 256>>>();
    proj2_kernel<<<NPAD / 64, 256>>>(bias1);
    gather2_kernel<<<(NN + 7) / 8, 256>>>(bias2, out);
}